// round 1
// baseline (speedup 1.0000x reference)
#include <cuda_runtime.h>
#include <math.h>
#include <stdint.h>

// MX fp8 (e4m3) fake quantization, block size 32, shared e8m0 exponent.
//
// Layout: flattened input, blocks of 32 consecutive floats share an exponent.
// Each warp handles 4 blocks: lanes are grouped 8-wide, each lane owns one
// float4 (4 elements). amax reduction = 3 shfl.bfly levels within the 8-lane
// group. All exponent math done on fp32 bit patterns (exact), scales are
// powers of two so divides become exact multiplies.

static __device__ __forceinline__ float qdq_elem(float x, float inv_scale,
                                                 float scale) {
    float xs = x * inv_scale;                       // exact (power-of-2 scale)
    int bits = __float_as_int(xs) & 0x7fffffff;     // |xs| bits
    int e = bits >> 23;                             // biased exponent field
    // priv_exp = max(floor(log2(|xs|)), -6). e==0 (zero/subnormal) maps to
    // -127 which the max() clamps to -6, matching the reference's TINY path.
    int pe = max(e - 127, -6);
    // pscale = 2^(pe-3), inv_pscale = 2^-(pe-3). pe in [-6, ~9] here, so both
    // exponents are comfortably in normal range -> bit-construct.
    float ps  = __int_as_float((pe - 3 + 127) << 23);
    float ips = __int_as_float((127 - (pe - 3)) << 23);
    float q = rintf(xs * ips) * ps;                 // round half-to-even
    q = fminf(fmaxf(q, -448.0f), 448.0f);           // saturate to e4m3 max
    return q * scale;
}

__global__ void mx_fp8_fq_kernel(const float4* __restrict__ in,
                                 float4* __restrict__ out, int n4) {
    int i = blockIdx.x * blockDim.x + threadIdx.x;
    if (i >= n4) return;

    float4 v = in[i];

    // per-thread amax over its 4 elements
    float a = fmaxf(fmaxf(fabsf(v.x), fabsf(v.y)),
                    fmaxf(fabsf(v.z), fabsf(v.w)));
    // reduce across the 8 lanes of this quant block (lanes i..i|7)
    a = fmaxf(a, __shfl_xor_sync(0xffffffffu, a, 1));
    a = fmaxf(a, __shfl_xor_sync(0xffffffffu, a, 2));
    a = fmaxf(a, __shfl_xor_sync(0xffffffffu, a, 4));

    // shared_exp = clip(floor(log2(amax or TINY)) - 8, -127, 127)
    int abits = __float_as_int(a);                  // a >= 0 -> no sign bit
    int e = abits >> 23;
    int se;
    if (e != 0) {
        se = e - 127;                               // normal: exact floor(log2)
    } else {
        se = (a == 0.0f) ? -126 : ilogbf(a);        // TINY path / subnormal
    }
    int sexp = se - 8;
    sexp = max(-127, min(127, sexp));

    // scale = 2^sexp (may be subnormal at sexp = -127 -> ldexpf handles it),
    // inv_scale = 2^-sexp (always normal since sexp >= -127 and, for any
    // finite fp32 amax, sexp <= 120).
    float scale = ldexpf(1.0f, sexp);
    float inv_scale = ldexpf(1.0f, -sexp);

    float4 r;
    r.x = qdq_elem(v.x, inv_scale, scale);
    r.y = qdq_elem(v.y, inv_scale, scale);
    r.z = qdq_elem(v.z, inv_scale, scale);
    r.w = qdq_elem(v.w, inv_scale, scale);
    out[i] = r;
}

extern "C" void kernel_launch(void* const* d_in, const int* in_sizes, int n_in,
                              void* d_out, int out_size) {
    const float4* in = (const float4*)d_in[0];
    float4* out = (float4*)d_out;
    int n = in_sizes[0];          // 8192*8192, divisible by 128
    int n4 = n / 4;
    int threads = 256;
    int blocks = (n4 + threads - 1) / threads;
    mx_fp8_fq_kernel<<<blocks, threads>>>(in, out, n4);
}

// round 2
// speedup vs baseline: 1.0546x; 1.0546x over previous
#include <cuda_runtime.h>
#include <stdint.h>

// MX fp8 (e4m3) fake quantization, block=32, shared e8m0 exponent.
//
// Warp layout: each warp owns 512 consecutive floats (128 float4, 16 blocks).
// Each lane does 4 coalesced float4 loads (j*32 + lane). Load j of the 8-lane
// group g covers block 4j+g. Block amax only matters via its fp32 exponent
// field, so we pack the 4 per-load exponent bytes into one u32 and reduce all
// 4 blocks at once with 3x shfl.bfly + per-byte max (__vmaxu4).
//
// Exponent-field max == exponent field of amax (nonneg floats). e-field==0
// (zero/subnormal amax) maps to sexp=-127, which matches the reference for
// both amax==0 (floor(log2(TINY))-8=-134 -> clip -127) and subnormal amax
// (<= -135 -> clip -127).

static __device__ __forceinline__ float qdq_elem(float x, float inv_scale,
                                                 float scale) {
    float xs = x * inv_scale;                        // exact (power-of-2)
    int e = (__float_as_int(xs) & 0x7fffffff) >> 23; // biased exp of |xs|
    int pe = max(e - 127, -6);                       // priv exp, clamped
    float ps  = __int_as_float((pe - 3 + 127) << 23);  // 2^(pe-3)
    float ips = __int_as_float((127 - (pe - 3)) << 23);// 2^-(pe-3)
    float q = rintf(xs * ips) * ps;                  // round half-to-even
    q = fminf(fmaxf(q, -448.0f), 448.0f);            // e4m3 saturate
    return q * scale;
}

__global__ void __launch_bounds__(256) mx_fp8_fq_kernel(
    const float4* __restrict__ in, float4* __restrict__ out, int n4) {
    int warp = (blockIdx.x * blockDim.x + threadIdx.x) >> 5;
    int lane = threadIdx.x & 31;
    int idx0 = warp * 128 + lane;        // float4 index of load j=0
    if (idx0 + 96 >= n4 && idx0 >= n4) return;   // exact-fit grid; cheap guard

    // Front-batched loads: 4 LDG.128 in flight per thread.
    float4 v0 = __ldcs(&in[idx0]);
    float4 v1 = __ldcs(&in[idx0 + 32]);
    float4 v2 = __ldcs(&in[idx0 + 64]);
    float4 v3 = __ldcs(&in[idx0 + 96]);

    // Per-load amax -> exponent byte, packed 4 blocks per u32.
    float a0 = fmaxf(fmaxf(fabsf(v0.x), fabsf(v0.y)), fmaxf(fabsf(v0.z), fabsf(v0.w)));
    float a1 = fmaxf(fmaxf(fabsf(v1.x), fabsf(v1.y)), fmaxf(fabsf(v1.z), fabsf(v1.w)));
    float a2 = fmaxf(fmaxf(fabsf(v2.x), fabsf(v2.y)), fmaxf(fabsf(v2.z), fabsf(v2.w)));
    float a3 = fmaxf(fmaxf(fabsf(v3.x), fabsf(v3.y)), fmaxf(fabsf(v3.z), fabsf(v3.w)));
    unsigned packed = (__float_as_uint(a0) >> 23)
                    | ((__float_as_uint(a1) >> 23) << 8)
                    | ((__float_as_uint(a2) >> 23) << 16)
                    | ((__float_as_uint(a3) >> 23) << 24);

    // Segmented (8-lane) reduction of all 4 block exponents at once.
    packed = __vmaxu4(packed, __shfl_xor_sync(0xffffffffu, packed, 1));
    packed = __vmaxu4(packed, __shfl_xor_sync(0xffffffffu, packed, 2));
    packed = __vmaxu4(packed, __shfl_xor_sync(0xffffffffu, packed, 4));

    float4 va[4] = {v0, v1, v2, v3};
#pragma unroll
    for (int j = 0; j < 4; j++) {
        int e = (packed >> (8 * j)) & 0xff;
        int sexp = max(e - 135, -127);   // floor(log2(amax)) - 8, clipped low
        // scale = 2^sexp; sexp==-127 needs the subnormal 0x00400000.
        float scale = __int_as_float(max((sexp + 127) << 23, 0x00400000));
        float inv   = __int_as_float((127 - sexp) << 23);   // 2^-sexp, normal
        float4 r;
        r.x = qdq_elem(va[j].x, inv, scale);
        r.y = qdq_elem(va[j].y, inv, scale);
        r.z = qdq_elem(va[j].z, inv, scale);
        r.w = qdq_elem(va[j].w, inv, scale);
        __stcs(&out[idx0 + 32 * j], r);
    }
}

extern "C" void kernel_launch(void* const* d_in, const int* in_sizes, int n_in,
                              void* d_out, int out_size) {
    const float4* in = (const float4*)d_in[0];
    float4* out = (float4*)d_out;
    int n = in_sizes[0];              // 8192*8192
    int n4 = n / 4;                   // 16,777,216 float4
    // 128 float4 per warp -> n4/128 warps; 256 threads = 8 warps per block.
    int warps = n4 / 128;
    int blocks = warps / 8;           // exact for this shape
    mx_fp8_fq_kernel<<<blocks, 256>>>(in, out, n4);
}